// round 14
// baseline (speedup 1.0000x reference)
#include <cuda_runtime.h>

#define NN 100000
#define DD 16
#define EE 3200000
#define LOG2E 1.4426950408889634f

// ---- scratch (device globals; .bss => zero at load) ----
// Champion layout: separate 64B-stride arrays; atomic targets never share
// a 128B line with gather-read data.
__device__ float4 g_fs1[NN * 4];
__device__ float4 g_fd1[NN * 4];
__device__ float4 g_fs2[NN * 4];
__device__ float4 g_fd2[NN * 4];
__device__ float4 g_acc[NN * 4];   // invariant: all-zero at kernel_launch entry
__device__ float  g_den[NN];       // invariant: all-zero at kernel_launch entry

__device__ __forceinline__ float lrelu(float x, float s) {
    return fmaxf(x, s * x);        // valid for 0 < s < 1
}

// ---------------------------------------------------------------------------
// Layer-1 node transform: fs1 = h@Ws+bs ; fd1 = h@Wd+bd
// ---------------------------------------------------------------------------
__global__ __launch_bounds__(256)
void transform1_kernel(const float* __restrict__ h,
                       const float* __restrict__ Ws, const float* __restrict__ bs,
                       const float* __restrict__ Wd, const float* __restrict__ bd)
{
    __shared__ float sWs[DD * DD], sWd[DD * DD], sbs[DD], sbd[DD];
    int t = threadIdx.x;
    if (t < DD * DD) { sWs[t] = Ws[t]; sWd[t] = Wd[t]; }
    if (t < DD)      { sbs[t] = bs[t]; sbd[t] = bd[t]; }
    __syncthreads();

    int i = blockIdx.x * 256 + t;
    if (i >= NN) return;

    float hr[DD];
    const float4* h4 = (const float4*)(h + (size_t)i * DD);
    #pragma unroll
    for (int q = 0; q < 4; q++) {
        float4 v = h4[q];
        hr[4*q+0] = v.x; hr[4*q+1] = v.y; hr[4*q+2] = v.z; hr[4*q+3] = v.w;
    }

    #pragma unroll
    for (int q = 0; q < 4; q++) {
        float as[4], ad[4];
        #pragma unroll
        for (int r = 0; r < 4; r++) {
            int j = 4*q + r;
            float a = sbs[j], b = sbd[j];
            #pragma unroll
            for (int k = 0; k < DD; k++) {
                a = fmaf(hr[k], sWs[k*DD + j], a);
                b = fmaf(hr[k], sWd[k*DD + j], b);
            }
            as[r] = a; ad[r] = b;
        }
        g_fs1[(size_t)i * 4 + q] = make_float4(as[0], as[1], as[2], as[3]);
        g_fd1[(size_t)i * 4 + q] = make_float4(ad[0], ad[1], ad[2], ad[3]);
    }
}

// ---------------------------------------------------------------------------
// Quad-per-edge kernel, 2 edges per quad (champion config).
// PDL: index/attn prologue runs before cudaGridDependencySynchronize(),
// overlapping the predecessor's tail wave.
// Grid is exact (EE*2 divisible by 256): no bounds guard needed.
// ---------------------------------------------------------------------------
__global__ __launch_bounds__(256)
void edge_kernel(const int2* __restrict__ src2, const int2* __restrict__ dst2,
                 const float* __restrict__ attn,
                 const float4* __restrict__ fs, const float4* __restrict__ fd)
{
    int tid = blockIdx.x * 256 + threadIdx.x;
    int g = tid >> 2;            // quad id: handles edges 2g, 2g+1
    int q = threadIdx.x & 3;     // float4 part within the 16-vector

    // independent prologue: harness inputs only
    float a0 = __ldg(&attn[4*q+0]) * LOG2E;
    float a1 = __ldg(&attn[4*q+1]) * LOG2E;
    float a2 = __ldg(&attn[4*q+2]) * LOG2E;
    float a3 = __ldg(&attn[4*q+3]) * LOG2E;

    int2 sv = __ldg(&src2[g]);
    int2 dv = __ldg(&dst2[g]);

    // wait for predecessor (transform/finalize) results
    cudaGridDependencySynchronize();

    // issue all four gathers up front (MLP)
    float4 A0 = fs[(size_t)sv.x * 4 + q];
    float4 B0 = fd[(size_t)dv.x * 4 + q];
    float4 A1 = fs[(size_t)sv.y * 4 + q];
    float4 B1 = fd[(size_t)dv.y * 4 + q];

    float p0;
    p0 = lrelu(A0.x + B0.x, 0.2f) * a0;
    p0 = fmaf(lrelu(A0.y + B0.y, 0.2f), a1, p0);
    p0 = fmaf(lrelu(A0.z + B0.z, 0.2f), a2, p0);
    p0 = fmaf(lrelu(A0.w + B0.w, 0.2f), a3, p0);

    float p1;
    p1 = lrelu(A1.x + B1.x, 0.2f) * a0;
    p1 = fmaf(lrelu(A1.y + B1.y, 0.2f), a1, p1);
    p1 = fmaf(lrelu(A1.z + B1.z, 0.2f), a2, p1);
    p1 = fmaf(lrelu(A1.w + B1.w, 0.2f), a3, p1);

    // intra-quad reduce (xor 1, 2 stays inside the quad)
    p0 += __shfl_xor_sync(0xFFFFFFFFu, p0, 1);
    p0 += __shfl_xor_sync(0xFFFFFFFFu, p0, 2);
    p1 += __shfl_xor_sync(0xFFFFFFFFu, p1, 1);
    p1 += __shfl_xor_sync(0xFFFFFFFFu, p1, 2);

    float ex0 = exp2f(p0);
    float ex1 = exp2f(p1);

    asm volatile("red.global.add.v4.f32 [%0], {%1, %2, %3, %4};"
                 :: "l"(&g_acc[(size_t)dv.x * 4 + q]),
                    "f"(ex0*A0.x), "f"(ex0*A0.y), "f"(ex0*A0.z), "f"(ex0*A0.w)
                 : "memory");
    asm volatile("red.global.add.v4.f32 [%0], {%1, %2, %3, %4};"
                 :: "l"(&g_acc[(size_t)dv.y * 4 + q]),
                    "f"(ex1*A1.x), "f"(ex1*A1.y), "f"(ex1*A1.z), "f"(ex1*A1.w)
                 : "memory");

    // den reds: one predicated instruction, lanes 0/1 of each quad
    if (q < 2) {
        float exq = (q == 0) ? ex0 : ex1;
        int   dq  = (q == 0) ? dv.x : dv.y;
        asm volatile("red.global.add.f32 [%0], %1;"
                     :: "l"(&g_den[dq]), "f"(exq) : "memory");
    }

    cudaTriggerProgrammaticLaunchCompletion();
}

// ---------------------------------------------------------------------------
// Finalize layer 1 + fused layer-2 transform. Re-zeros acc/den in place.
// PDL: weight staging overlaps edge1's tail.
// ---------------------------------------------------------------------------
__global__ __launch_bounds__(256)
void finalize1_kernel(const float* __restrict__ Ws2, const float* __restrict__ bs2,
                      const float* __restrict__ Wd2, const float* __restrict__ bd2)
{
    __shared__ float sWs[DD * DD], sWd[DD * DD], sbs[DD], sbd[DD];
    int t = threadIdx.x;
    if (t < DD * DD) { sWs[t] = Ws2[t]; sWd[t] = Wd2[t]; }
    if (t < DD)      { sbs[t] = bs2[t]; sbd[t] = bd2[t]; }
    __syncthreads();

    // wait for edge1's reductions before reading acc/den
    cudaGridDependencySynchronize();

    int i = blockIdx.x * 256 + t;
    if (i >= NN) return;

    float den = g_den[i];
    g_den[i] = 0.f;
    float inv = (den > 0.f) ? (1.f / den) : 0.f;

    float row[DD];
    const float4 z4 = make_float4(0.f, 0.f, 0.f, 0.f);
    #pragma unroll
    for (int q = 0; q < 4; q++) {
        float4 v = g_acc[(size_t)i * 4 + q];
        g_acc[(size_t)i * 4 + q] = z4;
        row[4*q+0] = lrelu(v.x * inv, 0.01f);
        row[4*q+1] = lrelu(v.y * inv, 0.01f);
        row[4*q+2] = lrelu(v.z * inv, 0.01f);
        row[4*q+3] = lrelu(v.w * inv, 0.01f);
    }

    #pragma unroll
    for (int q = 0; q < 4; q++) {
        float as[4], ad[4];
        #pragma unroll
        for (int r = 0; r < 4; r++) {
            int j = 4*q + r;
            float a = sbs[j], b = sbd[j];
            #pragma unroll
            for (int k = 0; k < DD; k++) {
                a = fmaf(row[k], sWs[k*DD + j], a);
                b = fmaf(row[k], sWd[k*DD + j], b);
            }
            as[r] = a; ad[r] = b;
        }
        g_fs2[(size_t)i * 4 + q] = make_float4(as[0], as[1], as[2], as[3]);
        g_fd2[(size_t)i * 4 + q] = make_float4(ad[0], ad[1], ad[2], ad[3]);
    }
}

// ---------------------------------------------------------------------------
// Finalize layer 2 -> output. Re-zeros acc/den (restores invariant).
// ---------------------------------------------------------------------------
__global__ __launch_bounds__(256)
void finalize2_kernel(float* __restrict__ out)
{
    cudaGridDependencySynchronize();

    int i = blockIdx.x * 256 + threadIdx.x;
    if (i >= NN) return;

    float den = g_den[i];
    g_den[i] = 0.f;
    float inv = (den > 0.f) ? (1.f / den) : 0.f;

    const float4 z4 = make_float4(0.f, 0.f, 0.f, 0.f);
    float4* o4 = (float4*)(out + (size_t)i * DD);
    #pragma unroll
    for (int q = 0; q < 4; q++) {
        float4 v = g_acc[(size_t)i * 4 + q];
        g_acc[(size_t)i * 4 + q] = z4;
        float4 r;
        r.x = lrelu(v.x * inv, 0.01f);
        r.y = lrelu(v.y * inv, 0.01f);
        r.z = lrelu(v.z * inv, 0.01f);
        r.w = lrelu(v.w * inv, 0.01f);
        o4[q] = r;
    }
}

// ---------------------------------------------------------------------------
// Launch helpers: kernels 2-5 use programmatic stream serialization (PDL).
// ---------------------------------------------------------------------------
template <typename K, typename... Args>
static void launch_pdl(K kernel, dim3 grid, dim3 block, Args... args)
{
    cudaLaunchConfig_t cfg = {};
    cfg.gridDim = grid;
    cfg.blockDim = block;
    cfg.dynamicSmemBytes = 0;
    cfg.stream = 0;
    cudaLaunchAttribute attr[1];
    attr[0].id = cudaLaunchAttributeProgrammaticStreamSerialization;
    attr[0].val.programmaticStreamSerializationAllowed = 1;
    cfg.attrs = attr;
    cfg.numAttrs = 1;
    cudaLaunchKernelEx(&cfg, kernel, args...);
}

extern "C" void kernel_launch(void* const* d_in, const int* in_sizes, int n_in,
                              void* d_out, int out_size)
{
    const float* emb  = (const float*)d_in[0];
    const int*   src1 = (const int*)  d_in[1];
    const int*   dst1 = (const int*)  d_in[2];
    const int*   src2 = (const int*)  d_in[3];
    const int*   dst2 = (const int*)  d_in[4];
    const float* Ws1  = (const float*)d_in[5];
    const float* bs1  = (const float*)d_in[6];
    const float* Wd1  = (const float*)d_in[7];
    const float* bd1  = (const float*)d_in[8];
    const float* at1  = (const float*)d_in[9];
    const float* Ws2  = (const float*)d_in[10];
    const float* bs2  = (const float*)d_in[11];
    const float* Wd2  = (const float*)d_in[12];
    const float* bd2  = (const float*)d_in[13];
    const float* at2  = (const float*)d_in[14];
    float* out = (float*)d_out;

    float4 *p_fs1, *p_fd1, *p_fs2, *p_fd2;
    cudaGetSymbolAddress((void**)&p_fs1, g_fs1);
    cudaGetSymbolAddress((void**)&p_fd1, g_fd1);
    cudaGetSymbolAddress((void**)&p_fs2, g_fs2);
    cudaGetSymbolAddress((void**)&p_fd2, g_fd2);

    const int TB = 256;
    dim3 blk(TB);
    dim3 gN((NN + TB - 1) / TB);
    dim3 gE((EE * 2 + TB - 1) / TB);   // 4 lanes/edge, 2 edges/quad (exact)

    transform1_kernel<<<gN, blk>>>(emb, Ws1, bs1, Wd1, bd1);
    launch_pdl(edge_kernel, gE, blk,
               (const int2*)src1, (const int2*)dst1, at1,
               (const float4*)p_fs1, (const float4*)p_fd1);
    launch_pdl(finalize1_kernel, gN, blk, Ws2, bs2, Wd2, bd2);
    launch_pdl(edge_kernel, gE, blk,
               (const int2*)src2, (const int2*)dst2, at2,
               (const float4*)p_fs2, (const float4*)p_fd2);
    launch_pdl(finalize2_kernel, gN, blk, out);
}

// round 15
// speedup vs baseline: 1.0113x; 1.0113x over previous
#include <cuda_runtime.h>

#define NN 100000
#define DD 16
#define EE 3200000
#define LOG2E 1.4426950408889634f

// ---- scratch (device globals; .bss => zero at load) ----
// Champion layout: separate 64B-stride arrays; atomic targets never share
// a 128B line with gather-read data.
__device__ float4 g_fs1[NN * 4];
__device__ float4 g_fd1[NN * 4];
__device__ float4 g_fs2[NN * 4];
__device__ float4 g_fd2[NN * 4];
__device__ float4 g_acc[NN * 4];   // invariant: all-zero at kernel_launch entry
__device__ float  g_den[NN];       // invariant: all-zero at kernel_launch entry

__device__ __forceinline__ float lrelu(float x, float s) {
    return fmaxf(x, s * x);        // valid for 0 < s < 1
}

// ---------------------------------------------------------------------------
// Layer-1 node transform: fs1 = h@Ws+bs ; fd1 = h@Wd+bd
// ---------------------------------------------------------------------------
__global__ __launch_bounds__(256)
void transform1_kernel(const float* __restrict__ h,
                       const float* __restrict__ Ws, const float* __restrict__ bs,
                       const float* __restrict__ Wd, const float* __restrict__ bd)
{
    __shared__ float sWs[DD * DD], sWd[DD * DD], sbs[DD], sbd[DD];
    int t = threadIdx.x;
    if (t < DD * DD) { sWs[t] = Ws[t]; sWd[t] = Wd[t]; }
    if (t < DD)      { sbs[t] = bs[t]; sbd[t] = bd[t]; }
    __syncthreads();

    int i = blockIdx.x * 256 + t;
    if (i >= NN) return;

    float hr[DD];
    const float4* h4 = (const float4*)(h + (size_t)i * DD);
    #pragma unroll
    for (int q = 0; q < 4; q++) {
        float4 v = h4[q];
        hr[4*q+0] = v.x; hr[4*q+1] = v.y; hr[4*q+2] = v.z; hr[4*q+3] = v.w;
    }

    #pragma unroll
    for (int q = 0; q < 4; q++) {
        float as[4], ad[4];
        #pragma unroll
        for (int r = 0; r < 4; r++) {
            int j = 4*q + r;
            float a = sbs[j], b = sbd[j];
            #pragma unroll
            for (int k = 0; k < DD; k++) {
                a = fmaf(hr[k], sWs[k*DD + j], a);
                b = fmaf(hr[k], sWd[k*DD + j], b);
            }
            as[r] = a; ad[r] = b;
        }
        g_fs1[(size_t)i * 4 + q] = make_float4(as[0], as[1], as[2], as[3]);
        g_fd1[(size_t)i * 4 + q] = make_float4(ad[0], ad[1], ad[2], ad[3]);
    }
}

// ---------------------------------------------------------------------------
// Quad-per-edge kernel, 2 edges per quad (champion config).
// PDL: index/attn prologue runs before cudaGridDependencySynchronize(),
// overlapping the predecessor's tail wave.
// ---------------------------------------------------------------------------
__global__ __launch_bounds__(256)
void edge_kernel(const int2* __restrict__ src2, const int2* __restrict__ dst2,
                 const float* __restrict__ attn,
                 const float4* __restrict__ fs, const float4* __restrict__ fd)
{
    int tid = blockIdx.x * 256 + threadIdx.x;
    int g = tid >> 2;            // quad id: handles edges 2g, 2g+1
    int q = threadIdx.x & 3;     // float4 part within the 16-vector
    if (2 * g >= EE) {
        cudaGridDependencySynchronize();
        return;
    }

    // independent prologue: harness inputs only
    float a0 = __ldg(&attn[4*q+0]) * LOG2E;
    float a1 = __ldg(&attn[4*q+1]) * LOG2E;
    float a2 = __ldg(&attn[4*q+2]) * LOG2E;
    float a3 = __ldg(&attn[4*q+3]) * LOG2E;

    int2 sv = __ldg(&src2[g]);
    int2 dv = __ldg(&dst2[g]);

    // wait for predecessor (transform/finalize) results
    cudaGridDependencySynchronize();

    // issue all four gathers up front (MLP)
    float4 A0 = fs[(size_t)sv.x * 4 + q];
    float4 B0 = fd[(size_t)dv.x * 4 + q];
    float4 A1 = fs[(size_t)sv.y * 4 + q];
    float4 B1 = fd[(size_t)dv.y * 4 + q];

    float p0;
    p0 = lrelu(A0.x + B0.x, 0.2f) * a0;
    p0 = fmaf(lrelu(A0.y + B0.y, 0.2f), a1, p0);
    p0 = fmaf(lrelu(A0.z + B0.z, 0.2f), a2, p0);
    p0 = fmaf(lrelu(A0.w + B0.w, 0.2f), a3, p0);

    float p1;
    p1 = lrelu(A1.x + B1.x, 0.2f) * a0;
    p1 = fmaf(lrelu(A1.y + B1.y, 0.2f), a1, p1);
    p1 = fmaf(lrelu(A1.z + B1.z, 0.2f), a2, p1);
    p1 = fmaf(lrelu(A1.w + B1.w, 0.2f), a3, p1);

    // intra-quad reduce (xor 1, 2 stays inside the quad)
    p0 += __shfl_xor_sync(0xFFFFFFFFu, p0, 1);
    p0 += __shfl_xor_sync(0xFFFFFFFFu, p0, 2);
    p1 += __shfl_xor_sync(0xFFFFFFFFu, p1, 1);
    p1 += __shfl_xor_sync(0xFFFFFFFFu, p1, 2);

    float ex0 = exp2f(p0);
    float ex1 = exp2f(p1);

    asm volatile("red.global.add.v4.f32 [%0], {%1, %2, %3, %4};"
                 :: "l"(&g_acc[(size_t)dv.x * 4 + q]),
                    "f"(ex0*A0.x), "f"(ex0*A0.y), "f"(ex0*A0.z), "f"(ex0*A0.w)
                 : "memory");
    asm volatile("red.global.add.v4.f32 [%0], {%1, %2, %3, %4};"
                 :: "l"(&g_acc[(size_t)dv.y * 4 + q]),
                    "f"(ex1*A1.x), "f"(ex1*A1.y), "f"(ex1*A1.z), "f"(ex1*A1.w)
                 : "memory");

    // den reds: one predicated instruction, lanes 0/1 of each quad
    if (q < 2) {
        float exq = (q == 0) ? ex0 : ex1;
        int   dq  = (q == 0) ? dv.x : dv.y;
        asm volatile("red.global.add.f32 [%0], %1;"
                     :: "l"(&g_den[dq]), "f"(exq) : "memory");
    }
}

// ---------------------------------------------------------------------------
// Finalize layer 1 + fused layer-2 transform. Re-zeros acc/den in place.
// PDL: weight staging overlaps edge1's tail.
// ---------------------------------------------------------------------------
__global__ __launch_bounds__(256)
void finalize1_kernel(const float* __restrict__ Ws2, const float* __restrict__ bs2,
                      const float* __restrict__ Wd2, const float* __restrict__ bd2)
{
    __shared__ float sWs[DD * DD], sWd[DD * DD], sbs[DD], sbd[DD];
    int t = threadIdx.x;
    if (t < DD * DD) { sWs[t] = Ws2[t]; sWd[t] = Wd2[t]; }
    if (t < DD)      { sbs[t] = bs2[t]; sbd[t] = bd2[t]; }
    __syncthreads();

    // wait for edge1's reductions before reading acc/den
    cudaGridDependencySynchronize();

    int i = blockIdx.x * 256 + t;
    if (i >= NN) return;

    float den = g_den[i];
    g_den[i] = 0.f;
    float inv = (den > 0.f) ? (1.f / den) : 0.f;

    float row[DD];
    const float4 z4 = make_float4(0.f, 0.f, 0.f, 0.f);
    #pragma unroll
    for (int q = 0; q < 4; q++) {
        float4 v = g_acc[(size_t)i * 4 + q];
        g_acc[(size_t)i * 4 + q] = z4;
        row[4*q+0] = lrelu(v.x * inv, 0.01f);
        row[4*q+1] = lrelu(v.y * inv, 0.01f);
        row[4*q+2] = lrelu(v.z * inv, 0.01f);
        row[4*q+3] = lrelu(v.w * inv, 0.01f);
    }

    #pragma unroll
    for (int q = 0; q < 4; q++) {
        float as[4], ad[4];
        #pragma unroll
        for (int r = 0; r < 4; r++) {
            int j = 4*q + r;
            float a = sbs[j], b = sbd[j];
            #pragma unroll
            for (int k = 0; k < DD; k++) {
                a = fmaf(row[k], sWs[k*DD + j], a);
                b = fmaf(row[k], sWd[k*DD + j], b);
            }
            as[r] = a; ad[r] = b;
        }
        g_fs2[(size_t)i * 4 + q] = make_float4(as[0], as[1], as[2], as[3]);
        g_fd2[(size_t)i * 4 + q] = make_float4(ad[0], ad[1], ad[2], ad[3]);
    }
}

// ---------------------------------------------------------------------------
// Finalize layer 2 -> output. Re-zeros acc/den (restores invariant).
// ---------------------------------------------------------------------------
__global__ __launch_bounds__(256)
void finalize2_kernel(float* __restrict__ out)
{
    cudaGridDependencySynchronize();

    int i = blockIdx.x * 256 + threadIdx.x;
    if (i >= NN) return;

    float den = g_den[i];
    g_den[i] = 0.f;
    float inv = (den > 0.f) ? (1.f / den) : 0.f;

    const float4 z4 = make_float4(0.f, 0.f, 0.f, 0.f);
    float4* o4 = (float4*)(out + (size_t)i * DD);
    #pragma unroll
    for (int q = 0; q < 4; q++) {
        float4 v = g_acc[(size_t)i * 4 + q];
        g_acc[(size_t)i * 4 + q] = z4;
        float4 r;
        r.x = lrelu(v.x * inv, 0.01f);
        r.y = lrelu(v.y * inv, 0.01f);
        r.z = lrelu(v.z * inv, 0.01f);
        r.w = lrelu(v.w * inv, 0.01f);
        o4[q] = r;
    }
}

// ---------------------------------------------------------------------------
// Launch helpers: kernels 2-5 use programmatic stream serialization (PDL).
// ---------------------------------------------------------------------------
template <typename K, typename... Args>
static void launch_pdl(K kernel, dim3 grid, dim3 block, Args... args)
{
    cudaLaunchConfig_t cfg = {};
    cfg.gridDim = grid;
    cfg.blockDim = block;
    cfg.dynamicSmemBytes = 0;
    cfg.stream = 0;
    cudaLaunchAttribute attr[1];
    attr[0].id = cudaLaunchAttributeProgrammaticStreamSerialization;
    attr[0].val.programmaticStreamSerializationAllowed = 1;
    cfg.attrs = attr;
    cfg.numAttrs = 1;
    cudaLaunchKernelEx(&cfg, kernel, args...);
}

extern "C" void kernel_launch(void* const* d_in, const int* in_sizes, int n_in,
                              void* d_out, int out_size)
{
    const float* emb  = (const float*)d_in[0];
    const int*   src1 = (const int*)  d_in[1];
    const int*   dst1 = (const int*)  d_in[2];
    const int*   src2 = (const int*)  d_in[3];
    const int*   dst2 = (const int*)  d_in[4];
    const float* Ws1  = (const float*)d_in[5];
    const float* bs1  = (const float*)d_in[6];
    const float* Wd1  = (const float*)d_in[7];
    const float* bd1  = (const float*)d_in[8];
    const float* at1  = (const float*)d_in[9];
    const float* Ws2  = (const float*)d_in[10];
    const float* bs2  = (const float*)d_in[11];
    const float* Wd2  = (const float*)d_in[12];
    const float* bd2  = (const float*)d_in[13];
    const float* at2  = (const float*)d_in[14];
    float* out = (float*)d_out;

    float4 *p_fs1, *p_fd1, *p_fs2, *p_fd2;
    cudaGetSymbolAddress((void**)&p_fs1, g_fs1);
    cudaGetSymbolAddress((void**)&p_fd1, g_fd1);
    cudaGetSymbolAddress((void**)&p_fs2, g_fs2);
    cudaGetSymbolAddress((void**)&p_fd2, g_fd2);

    const int TB = 256;
    dim3 blk(TB);
    dim3 gN((NN + TB - 1) / TB);
    dim3 gE((EE * 2 + TB - 1) / TB);   // 4 lanes/edge, 2 edges/quad

    transform1_kernel<<<gN, blk>>>(emb, Ws1, bs1, Wd1, bd1);
    launch_pdl(edge_kernel, gE, blk,
               (const int2*)src1, (const int2*)dst1, at1,
               (const float4*)p_fs1, (const float4*)p_fd1);
    launch_pdl(finalize1_kernel, gN, blk, Ws2, bs2, Wd2, bd2);
    launch_pdl(edge_kernel, gE, blk,
               (const int2*)src2, (const int2*)dst2, at2,
               (const float4*)p_fs2, (const float4*)p_fd2);
    launch_pdl(finalize2_kernel, gN, blk, out);
}